// round 6
// baseline (speedup 1.0000x reference)
#include <cuda_runtime.h>
#include <cuda_fp16.h>
#include <cstdint>

#define NVOX   (2*96*96*64)   // 1179648
#define TPB    128
#define NTILES (NVOX / TPB)   // 9216
#define KCOMP  16
#define NFEAT  576
#define NKSTEP 36
#define DYN_SMEM 52288        // 2x16KB Z + 18KB W + a2 + 1KB align slack

static __device__ float g_Wtmp[KCOMP * NFEAT];
static __device__ uint2 g_Wfrag[NKSTEP * 2 * 32];  // [kstep][ntile][lane]
static __device__ float g_a2[KCOMP];

// ---------------- PTX helpers ----------------------------------------------
__device__ __forceinline__ uint32_t smem_u32(const void* p) {
    uint32_t a;
    asm("{ .reg .u64 t; cvta.to.shared.u64 t, %1; cvt.u32.u64 %0, t; }"
        : "=r"(a) : "l"(p));
    return a;
}
#define STS128(r0, r1, r2, r3, a) \
    asm volatile("st.shared.v4.b32 [%0], {%1, %2, %3, %4};" \
                 :: "r"(a), "r"(r0), "r"(r1), "r"(r2), "r"(r3) : "memory")

__device__ __forceinline__ void ldm4(uint32_t* r, uint32_t addr) {
    asm volatile("ldmatrix.sync.aligned.m8n8.x4.shared.b16 {%0,%1,%2,%3}, [%4];"
        : "=r"(r[0]), "=r"(r[1]), "=r"(r[2]), "=r"(r[3]) : "r"(addr));
}
__device__ __forceinline__ void mma16816(float* d, const uint32_t* a,
                                         const uint32_t* b, const float* c) {
    asm volatile("mma.sync.aligned.m16n8k16.row.col.f32.f16.f16.f32 "
        "{%0,%1,%2,%3}, {%4,%5,%6,%7}, {%8,%9}, {%10,%11,%12,%13};"
        : "=f"(d[0]), "=f"(d[1]), "=f"(d[2]), "=f"(d[3])
        : "r"(a[0]), "r"(a[1]), "r"(a[2]), "r"(a[3]),
          "r"(b[0]), "r"(b[1]),
          "f"(c[0]), "f"(c[1]), "f"(c[2]), "f"(c[3]));
}

// ---------------- fused prep: 1 block, 16 warps (warp = component) ---------
__global__ void __launch_bounds__(512)
prep_kernel(const float* __restrict__ wbg,  const float* __restrict__ mubg,
            const float* __restrict__ Lbg,  const float* __restrict__ wfg,
            const float* __restrict__ mufg, const float* __restrict__ Lfg) {
    __shared__ float sT[KCOMP * 528];   // L triangle, overwritten by Linv
    __shared__ float sb[KCOMP * 32];
    int w = threadIdx.x >> 5;   // component
    int j = threadIdx.x & 31;   // column / lane
    const float* L  = (w < 8) ? (Lbg  + w * 1024) : (Lfg  + (w - 8) * 1024);
    const float* mu = (w < 8) ? (mubg + w * 32)   : (mufg + (w - 8) * 32);
    float* tk = sT + w * 528;

    // load lower triangle of L (lane j loads column j)
    for (int r = j; r < 32; ++r) tk[r * (r + 1) / 2 + j] = L[r * 32 + j];
    __syncwarp();
    float Ldiag = tk[j * (j + 1) / 2 + j];

    // forward substitution: column j of Linv, fully register-resident
    float vv[32];
#pragma unroll
    for (int r = 0; r < 32; ++r) {
        float s = 0.0f;
#pragma unroll
        for (int m = 0; m < r; ++m) s += tk[r * (r + 1) / 2 + m] * vv[m];
        float d = tk[r * (r + 1) / 2 + r];
        vv[r] = (r < j) ? 0.0f : ((r == j) ? 1.0f / d : -s / d);
    }
    __syncwarp();
    // overwrite L triangle with Linv (all lanes done reading L)
    for (int r = j; r < 32; ++r) tk[r * (r + 1) / 2 + j] = vv[r];
    __syncwarp();

    // b_j = (Linv mu)_j
    float bj = 0.0f;
    {
        const float* row = tk + j * (j + 1) / 2;
        for (int c = 0; c <= j; ++c) bj += row[c] * mu[c];
    }
    sb[w * 32 + j] = bj;
    __syncwarp();

    const float inv400 = 0.0025f;
    // linear coeff: +2 (Linv^T b)_j / 400
    float q = 0.0f;
    for (int d = j; d < 32; ++d) q += tk[d * (d + 1) / 2 + j] * sb[w * 32 + d];
    g_Wtmp[w * NFEAT + 528 + j] = 2.0f * q * inv400;
    if (j < 16) g_Wtmp[w * NFEAT + 560 + j] = 0.0f;

    // quadratic coeffs
    for (int e = j; e < 528; e += 32) {
        int i = (int)((sqrtf(8.0f * e + 1.0f) - 1.0f) * 0.5f);
        while ((i + 1) * (i + 2) / 2 <= e) ++i;
        while (i * (i + 1) / 2 > e) --i;
        int jj = e - i * (i + 1) / 2;
        float p = 0.0f;
        for (int d = i; d < 32; ++d)
            p += tk[d * (d + 1) / 2 + i] * tk[d * (d + 1) / 2 + jj];
        g_Wtmp[w * NFEAT + e] = ((jj == i) ? -p : -2.0f * p) * inv400;
    }

    // a'_k via warp reduction of log(diag) and ||b||^2
    float lg = logf(Ldiag);
    float bb = bj * bj;
#pragma unroll
    for (int off = 16; off > 0; off >>= 1) {
        lg += __shfl_xor_sync(0xFFFFFFFFu, lg, off);
        bb += __shfl_xor_sync(0xFFFFFFFFu, bb, off);
    }
    if (j == 0) {
        float wk = (w < 8) ? wbg[w] : wfg[w - 8];
        const float cst = -0.5f * 32.0f * 1.8378770664093453f;
        g_a2[w] = wk * expf((cst - lg) * 0.005f - bb * inv400);
    }
    __syncthreads();

    // pack W into mma B-fragment layout
    for (int idx = threadIdx.x; idx < NKSTEP * 64; idx += 512) {
        int s = idx >> 6, rem = idx & 63, nt = rem >> 5, lane = rem & 31;
        int n = nt * 8 + (lane >> 2);
        int t0 = s * 16 + (lane & 3) * 2;
        const float* W = g_Wtmp + n * NFEAT;
        __half2 lo = __floats2half2_rn(W[t0], W[t0 + 1]);
        __half2 hi = __floats2half2_rn(W[t0 + 8], W[t0 + 9]);
        uint2 u;
        u.x = *(uint32_t*)&lo;
        u.y = *(uint32_t*)&hi;
        g_Wfrag[idx] = u;
    }
}

// ---------------- density: pipelined quadratic-feature GEMM ----------------
__global__ void __launch_bounds__(TPB)
density_kernel(const float* __restrict__ fm, float* __restrict__ out) {
    extern __shared__ char dsm[];
    uint32_t sraw = smem_u32(dsm);
    uint32_t Zbase = (sraw + 1023u) & ~1023u;
    char* p = dsm + (Zbase - sraw);
    uint2* sW = (uint2*)(p + 32768);
    float* sa2 = (float*)(p + 32768 + 18432);

    int tid = threadIdx.x;
    int lane = tid & 31;
    int wid = tid >> 5;

    {   // stage B fragments + a'
        uint4* dst = (uint4*)sW;
        const uint4* src = (const uint4*)g_Wfrag;
#pragma unroll
        for (int i = 0; i < 9; ++i) dst[tid + i * TPB] = src[tid + i * TPB];
        if (tid < KCOMP) sa2[tid] = g_a2[tid];
    }

    size_t v0 = (size_t)blockIdx.x * TPB;
    float x[32];
    {
        const float4* xf = (const float4*)(fm + (v0 + tid) * 32);
#pragma unroll
        for (int q = 0; q < 8; ++q) {
            float4 t4 = xf[q];
            x[4 * q + 0] = t4.x; x[4 * q + 1] = t4.y;
            x[4 * q + 2] = t4.z; x[4 * q + 3] = t4.w;
        }
    }

    uint32_t sts_row = Zbase + (uint32_t)tid * 128;
    uint32_t x7 = (uint32_t)(tid & 7);

    uint32_t lrow0 = (uint32_t)(wid * 32 + (lane & 7) + ((lane >> 3) & 1) * 8);
    uint32_t lrow1 = lrow0 + 16;
    uint32_t colsel = (uint32_t)(lane >> 4);
    uint32_t lx = lrow0 & 7;
    uint32_t l0off = lrow0 * 128;
    uint32_t l1off = lrow1 * 128;

    float acc[2][2][4];
#pragma unroll
    for (int a3 = 0; a3 < 2; ++a3)
#pragma unroll
        for (int b3 = 0; b3 < 2; ++b3)
#pragma unroll
            for (int c3 = 0; c3 < 4; ++c3) acc[a3][b3][c3] = 0.0f;

    float pend = 0.0f;
    uint32_t hh[4];

// sync; then consume chunk cc (ns ksteps) from buffer (cc&1). Feature gen of
// chunk cc+1 follows in program order and overlaps the HMMAs.
#define DO_CHUNK_N(cc, ns) do {                                                \
    __syncthreads();                                                           \
    uint32_t _zb = Zbase + (((cc) & 1) << 14);                                 \
    uint32_t _l0 = _zb + l0off;                                                \
    uint32_t _l1 = _zb + l1off;                                                \
    _Pragma("unroll")                                                          \
    for (int _s = 0; _s < (ns); ++_s) {                                        \
        int _sg = (cc) * 4 + _s;                                               \
        uint32_t _a0[4], _a1[4];                                               \
        uint32_t _cc = (uint32_t)(_s * 2) + colsel;                            \
        ldm4(_a0, _l0 + ((_cc ^ lx) << 4));                                    \
        ldm4(_a1, _l1 + ((_cc ^ lx) << 4));                                    \
        uint2 _b0 = sW[_sg * 64 + lane];                                       \
        uint2 _b1 = sW[_sg * 64 + 32 + lane];                                  \
        mma16816(acc[0][0], _a0, (uint32_t*)&_b0, acc[0][0]);                  \
        mma16816(acc[0][1], _a0, (uint32_t*)&_b1, acc[0][1]);                  \
        mma16816(acc[1][0], _a1, (uint32_t*)&_b0, acc[1][0]);                  \
        mma16816(acc[1][1], _a1, (uint32_t*)&_b1, acc[1][1]);                  \
    }                                                                          \
} while (0)

#define EMIT(tc, val) do {                                                     \
    const int _t = (tc); float _v = (val);                                     \
    if ((_t & 1) == 0) pend = _v;                                              \
    else {                                                                     \
        __half2 _h = __floats2half2_rn(pend, _v);                              \
        hh[(_t >> 1) & 3] = *(uint32_t*)&_h;                                   \
        if ((_t & 7) == 7) {                                                   \
            uint32_t _a = sts_row + ((((uint32_t)_t >> 6) & 1) << 14)          \
                          + (((((uint32_t)_t >> 3) & 7) ^ x7) << 4);           \
            STS128(hh[0], hh[1], hh[2], hh[3], _a);                            \
        }                                                                      \
        if ((_t & 63) == 63) DO_CHUNK_N(_t >> 6, 4);                           \
    }                                                                          \
} while (0)

    // quadratic monomials t = i(i+1)/2 + j (i >= j); boundaries fire at
    // t = 63,127,...,511 (chunks 0..7)
#pragma unroll
    for (int i2 = 0; i2 < 32; ++i2)
#pragma unroll
        for (int j2 = 0; j2 <= i2; ++j2)
            EMIT(i2 * (i2 + 1) / 2 + j2, x[i2] * x[j2]);
    // linear monomials t = 528..559 (chunk 8, ksteps 32..34; kstep 35 unused)
#pragma unroll
    for (int j2 = 0; j2 < 32; ++j2) EMIT(528 + j2, x[j2]);

    // final partial chunk: 3 ksteps (features 512..559)
    DO_CHUNK_N(8, 3);

#undef EMIT
#undef DO_CHUNK_N

    // epilogue: dens = sum_k a'_k exp(G)
    int g = lane >> 2, q = lane & 3;
    int c0 = q * 2;
    float w00 = sa2[c0], w01 = sa2[c0 + 1], w10 = sa2[c0 + 8], w11 = sa2[c0 + 9];
    float p0 = w00 * __expf(acc[0][0][0]) + w01 * __expf(acc[0][0][1])
             + w10 * __expf(acc[0][1][0]) + w11 * __expf(acc[0][1][1]);
    float p1 = w00 * __expf(acc[0][0][2]) + w01 * __expf(acc[0][0][3])
             + w10 * __expf(acc[0][1][2]) + w11 * __expf(acc[0][1][3]);
    float p2 = w00 * __expf(acc[1][0][0]) + w01 * __expf(acc[1][0][1])
             + w10 * __expf(acc[1][1][0]) + w11 * __expf(acc[1][1][1]);
    float p3 = w00 * __expf(acc[1][0][2]) + w01 * __expf(acc[1][0][3])
             + w10 * __expf(acc[1][1][2]) + w11 * __expf(acc[1][1][3]);

    p0 += __shfl_xor_sync(0xFFFFFFFFu, p0, 1); p0 += __shfl_xor_sync(0xFFFFFFFFu, p0, 2);
    p1 += __shfl_xor_sync(0xFFFFFFFFu, p1, 1); p1 += __shfl_xor_sync(0xFFFFFFFFu, p1, 2);
    p2 += __shfl_xor_sync(0xFFFFFFFFu, p2, 1); p2 += __shfl_xor_sync(0xFFFFFFFFu, p2, 2);
    p3 += __shfl_xor_sync(0xFFFFFFFFu, p3, 1); p3 += __shfl_xor_sync(0xFFFFFFFFu, p3, 2);

    if (q == 0) {
        size_t base = v0 + (size_t)wid * 32;
        size_t r0 = base + g, r1 = base + g + 8, r2 = base + g + 16, r3 = base + g + 24;
        out[r0] = ((r0 & 63) == 63) ? 0.0f : p0;
        out[r1] = ((r1 & 63) == 63) ? 0.0f : p1;
        out[r2] = ((r2 & 63) == 63) ? 0.0f : p2;
        out[r3] = ((r3 & 63) == 63) ? 0.0f : p3;
    }
}

// ---------------- launch ---------------------------------------------------
extern "C" void kernel_launch(void* const* d_in, const int* in_sizes, int n_in,
                              void* d_out, int out_size) {
    const float* fm   = (const float*)d_in[0];
    const float* wbg  = (const float*)d_in[1];
    const float* mubg = (const float*)d_in[2];
    const float* Lbg  = (const float*)d_in[3];
    const float* wfg  = (const float*)d_in[4];
    const float* mufg = (const float*)d_in[5];
    const float* Lfg  = (const float*)d_in[6];
    float* out = (float*)d_out;

    cudaFuncSetAttribute(density_kernel,
                         cudaFuncAttributeMaxDynamicSharedMemorySize, DYN_SMEM);

    prep_kernel<<<1, 512>>>(wbg, mubg, Lbg, wfg, mufg, Lfg);
    density_kernel<<<NTILES, TPB, DYN_SMEM>>>(fm, out);
}

// round 7
// speedup vs baseline: 1.1040x; 1.1040x over previous
#include <cuda_runtime.h>
#include <cuda_fp16.h>
#include <cstdint>

#define NVOX   (2*96*96*64)   // 1179648
#define TPB    128
#define NTILES (NVOX / TPB)   // 9216
#define KCOMP  16
#define NFEAT  576
#define NKSTEP 36

static __device__ float g_Wtmp[KCOMP * NFEAT];
static __device__ uint2 g_Wfrag[NKSTEP * 2 * 32];  // [kstep][ntile][lane]
static __device__ float g_a2[KCOMP];

// ---------------- PTX helpers ----------------------------------------------
__device__ __forceinline__ uint32_t smem_u32(const void* p) {
    uint32_t a;
    asm("{ .reg .u64 t; cvta.to.shared.u64 t, %1; cvt.u32.u64 %0, t; }"
        : "=r"(a) : "l"(p));
    return a;
}
#define STS128(r0, r1, r2, r3, a) \
    asm volatile("st.shared.v4.b32 [%0], {%1, %2, %3, %4};" \
                 :: "r"(a), "r"(r0), "r"(r1), "r"(r2), "r"(r3) : "memory")

__device__ __forceinline__ void ldm4(uint32_t* r, uint32_t addr) {
    asm volatile("ldmatrix.sync.aligned.m8n8.x4.shared.b16 {%0,%1,%2,%3}, [%4];"
        : "=r"(r[0]), "=r"(r[1]), "=r"(r[2]), "=r"(r[3]) : "r"(addr));
}
__device__ __forceinline__ void mma16816(float* d, const uint32_t* a,
                                         const uint32_t* b, const float* c) {
    asm volatile("mma.sync.aligned.m16n8k16.row.col.f32.f16.f16.f32 "
        "{%0,%1,%2,%3}, {%4,%5,%6,%7}, {%8,%9}, {%10,%11,%12,%13};"
        : "=f"(d[0]), "=f"(d[1]), "=f"(d[2]), "=f"(d[3])
        : "r"(a[0]), "r"(a[1]), "r"(a[2]), "r"(a[3]),
          "r"(b[0]), "r"(b[1]),
          "f"(c[0]), "f"(c[1]), "f"(c[2]), "f"(c[3]));
}

// ---------------- prep: 16 blocks (one per component) x 128 threads --------
__global__ void __launch_bounds__(128)
prep_kernel(const float* __restrict__ wbg,  const float* __restrict__ mubg,
            const float* __restrict__ Lbg,  const float* __restrict__ wfg,
            const float* __restrict__ mufg, const float* __restrict__ Lfg) {
    __shared__ float sL[528];   // L lower triangle
    __shared__ float sT[528];   // Linv lower triangle
    __shared__ float sb[32];
    int k = blockIdx.x;
    int tid = threadIdx.x;
    const float* L  = (k < 8) ? (Lbg  + k * 1024) : (Lfg  + (k - 8) * 1024);
    const float* mu = (k < 8) ? (mubg + k * 32)   : (mufg + (k - 8) * 32);

    // load L lower triangle
    for (int e = tid; e < 528; e += 128) {
        int i = (int)((sqrtf(8.0f * e + 1.0f) - 1.0f) * 0.5f);
        while ((i + 1) * (i + 2) / 2 <= e) ++i;
        while (i * (i + 1) / 2 > e) --i;
        int j = e - i * (i + 1) / 2;
        sL[e] = L[i * 32 + j];
    }
    __syncthreads();

    const float inv400 = 0.0025f;
    if (tid < 32) {
        int j = tid;
        // forward substitution: column j of Linv (registers)
        float vv[32];
#pragma unroll
        for (int r = 0; r < 32; ++r) {
            float s = 0.0f;
#pragma unroll
            for (int m = 0; m < r; ++m) s += sL[r * (r + 1) / 2 + m] * vv[m];
            float d = sL[r * (r + 1) / 2 + r];
            vv[r] = (r < j) ? 0.0f : ((r == j) ? 1.0f / d : -s / d);
        }
        for (int r = j; r < 32; ++r) sT[r * (r + 1) / 2 + j] = vv[r];
        __syncwarp();
        // b_j = (Linv mu)_j
        float bj = 0.0f;
        for (int c = 0; c <= j; ++c) bj += sT[j * (j + 1) / 2 + c] * mu[c];
        sb[j] = bj;
        __syncwarp();
        // linear coeff
        float q = 0.0f;
        for (int d = j; d < 32; ++d) q += sT[d * (d + 1) / 2 + j] * sb[d];
        g_Wtmp[k * NFEAT + 528 + j] = 2.0f * q * inv400;
        if (j < 16) g_Wtmp[k * NFEAT + 560 + j] = 0.0f;
        // a2 via warp reduction
        float lg = logf(sL[j * (j + 1) / 2 + j]);
        float bb = bj * bj;
#pragma unroll
        for (int off = 16; off > 0; off >>= 1) {
            lg += __shfl_xor_sync(0xFFFFFFFFu, lg, off);
            bb += __shfl_xor_sync(0xFFFFFFFFu, bb, off);
        }
        if (j == 0) {
            float wk = (k < 8) ? wbg[k] : wfg[k - 8];
            const float cst = -0.5f * 32.0f * 1.8378770664093453f;
            g_a2[k] = wk * expf((cst - lg) * 0.005f - bb * inv400);
        }
    }
    __syncthreads();

    // quadratic coeffs split across all 128 threads
    for (int e = tid; e < 528; e += 128) {
        int i = (int)((sqrtf(8.0f * e + 1.0f) - 1.0f) * 0.5f);
        while ((i + 1) * (i + 2) / 2 <= e) ++i;
        while (i * (i + 1) / 2 > e) --i;
        int jj = e - i * (i + 1) / 2;
        float p = 0.0f;
        for (int d = i; d < 32; ++d)
            p += sT[d * (d + 1) / 2 + i] * sT[d * (d + 1) / 2 + jj];
        g_Wtmp[k * NFEAT + e] = ((jj == i) ? -p : -2.0f * p) * inv400;
    }
}

// ---------------- pack W into mma B-fragment layout ------------------------
__global__ void pack_kernel() {
    int idx = blockIdx.x * blockDim.x + threadIdx.x;   // 2304 = 36*64
    int s = idx >> 6, rem = idx & 63, nt = rem >> 5, lane = rem & 31;
    int n = nt * 8 + (lane >> 2);
    int t0 = s * 16 + (lane & 3) * 2;
    const float* W = g_Wtmp + n * NFEAT;
    __half2 lo = __floats2half2_rn(W[t0], W[t0 + 1]);
    __half2 hi = __floats2half2_rn(W[t0 + 8], W[t0 + 9]);
    uint2 u;
    u.x = *(uint32_t*)&lo;
    u.y = *(uint32_t*)&hi;
    g_Wfrag[idx] = u;
}

// ---------------- density: pipelined quadratic-feature GEMM ----------------
__global__ void __launch_bounds__(TPB, 6)
density_kernel(const float* __restrict__ fm, float* __restrict__ out) {
    __shared__ __align__(128) char sZ[2 * 16384];    // Z double buffer

    int tid = threadIdx.x;
    int lane = tid & 31;
    int wid = tid >> 5;

    size_t v0 = (size_t)blockIdx.x * TPB;
    float x[32];
    {
        const float4* xf = (const float4*)(fm + (v0 + tid) * 32);
#pragma unroll
        for (int q = 0; q < 8; ++q) {
            float4 t4 = xf[q];
            x[4 * q + 0] = t4.x; x[4 * q + 1] = t4.y;
            x[4 * q + 2] = t4.z; x[4 * q + 3] = t4.w;
        }
    }

    uint32_t Zbase = smem_u32(sZ);
    uint32_t sts_row = Zbase + (uint32_t)tid * 128;
    uint32_t x7 = (uint32_t)(tid & 7);

    uint32_t lrow0 = (uint32_t)(wid * 32 + (lane & 7) + ((lane >> 3) & 1) * 8);
    uint32_t lrow1 = lrow0 + 16;
    uint32_t colsel = (uint32_t)(lane >> 4);
    uint32_t lx = lrow0 & 7;
    uint32_t l0off = lrow0 * 128;
    uint32_t l1off = lrow1 * 128;

    const uint2* __restrict__ gW = g_Wfrag;

    float acc[2][2][4];
#pragma unroll
    for (int a3 = 0; a3 < 2; ++a3)
#pragma unroll
        for (int b3 = 0; b3 < 2; ++b3)
#pragma unroll
            for (int c3 = 0; c3 < 4; ++c3) acc[a3][b3][c3] = 0.0f;

    float pend = 0.0f;
    uint32_t hh[4];

// sync; consume chunk cc (ns ksteps) from buffer (cc&1). Feature gen of the
// next chunk follows in program order and overlaps the HMMAs.
#define DO_CHUNK_N(cc, ns) do {                                                \
    __syncthreads();                                                           \
    uint32_t _zb = Zbase + (((cc) & 1) << 14);                                 \
    uint32_t _l0 = _zb + l0off;                                                \
    uint32_t _l1 = _zb + l1off;                                                \
    _Pragma("unroll")                                                          \
    for (int _s = 0; _s < (ns); ++_s) {                                        \
        int _sg = (cc) * 4 + _s;                                               \
        uint32_t _a0[4], _a1[4];                                               \
        uint32_t _cc = (uint32_t)(_s * 2) + colsel;                            \
        ldm4(_a0, _l0 + ((_cc ^ lx) << 4));                                    \
        ldm4(_a1, _l1 + ((_cc ^ lx) << 4));                                    \
        uint2 _b0 = __ldg(&gW[_sg * 64 + lane]);                               \
        uint2 _b1 = __ldg(&gW[_sg * 64 + 32 + lane]);                          \
        mma16816(acc[0][0], _a0, (uint32_t*)&_b0, acc[0][0]);                  \
        mma16816(acc[0][1], _a0, (uint32_t*)&_b1, acc[0][1]);                  \
        mma16816(acc[1][0], _a1, (uint32_t*)&_b0, acc[1][0]);                  \
        mma16816(acc[1][1], _a1, (uint32_t*)&_b1, acc[1][1]);                  \
    }                                                                          \
} while (0)

#define EMIT(tc, val) do {                                                     \
    const int _t = (tc); float _v = (val);                                     \
    if ((_t & 1) == 0) pend = _v;                                              \
    else {                                                                     \
        __half2 _h = __floats2half2_rn(pend, _v);                              \
        hh[(_t >> 1) & 3] = *(uint32_t*)&_h;                                   \
        if ((_t & 7) == 7) {                                                   \
            uint32_t _a = sts_row + ((((uint32_t)_t >> 6) & 1) << 14)          \
                          + (((((uint32_t)_t >> 3) & 7) ^ x7) << 4);           \
            STS128(hh[0], hh[1], hh[2], hh[3], _a);                            \
        }                                                                      \
        if ((_t & 63) == 63) DO_CHUNK_N(_t >> 6, 4);                           \
    }                                                                          \
} while (0)

    // quadratic monomials t = i(i+1)/2 + j (i >= j): chunks 0..7
#pragma unroll
    for (int i2 = 0; i2 < 32; ++i2)
#pragma unroll
        for (int j2 = 0; j2 <= i2; ++j2)
            EMIT(i2 * (i2 + 1) / 2 + j2, x[i2] * x[j2]);
    // linear monomials t = 528..559 (chunk 8, ksteps 32..34)
#pragma unroll
    for (int j2 = 0; j2 < 32; ++j2) EMIT(528 + j2, x[j2]);

    DO_CHUNK_N(8, 3);

#undef EMIT
#undef DO_CHUNK_N

    // epilogue: dens = sum_k a'_k exp(G)
    int g = lane >> 2, q = lane & 3;
    int c0 = q * 2;
    float w00 = __ldg(&g_a2[c0]);
    float w01 = __ldg(&g_a2[c0 + 1]);
    float w10 = __ldg(&g_a2[c0 + 8]);
    float w11 = __ldg(&g_a2[c0 + 9]);
    float p0 = w00 * __expf(acc[0][0][0]) + w01 * __expf(acc[0][0][1])
             + w10 * __expf(acc[0][1][0]) + w11 * __expf(acc[0][1][1]);
    float p1 = w00 * __expf(acc[0][0][2]) + w01 * __expf(acc[0][0][3])
             + w10 * __expf(acc[0][1][2]) + w11 * __expf(acc[0][1][3]);
    float p2 = w00 * __expf(acc[1][0][0]) + w01 * __expf(acc[1][0][1])
             + w10 * __expf(acc[1][1][0]) + w11 * __expf(acc[1][1][1]);
    float p3 = w00 * __expf(acc[1][0][2]) + w01 * __expf(acc[1][0][3])
             + w10 * __expf(acc[1][1][2]) + w11 * __expf(acc[1][1][3]);

    p0 += __shfl_xor_sync(0xFFFFFFFFu, p0, 1); p0 += __shfl_xor_sync(0xFFFFFFFFu, p0, 2);
    p1 += __shfl_xor_sync(0xFFFFFFFFu, p1, 1); p1 += __shfl_xor_sync(0xFFFFFFFFu, p1, 2);
    p2 += __shfl_xor_sync(0xFFFFFFFFu, p2, 1); p2 += __shfl_xor_sync(0xFFFFFFFFu, p2, 2);
    p3 += __shfl_xor_sync(0xFFFFFFFFu, p3, 1); p3 += __shfl_xor_sync(0xFFFFFFFFu, p3, 2);

    if (q == 0) {
        size_t base = v0 + (size_t)wid * 32;
        size_t r0 = base + g, r1 = base + g + 8, r2 = base + g + 16, r3 = base + g + 24;
        out[r0] = ((r0 & 63) == 63) ? 0.0f : p0;
        out[r1] = ((r1 & 63) == 63) ? 0.0f : p1;
        out[r2] = ((r2 & 63) == 63) ? 0.0f : p2;
        out[r3] = ((r3 & 63) == 63) ? 0.0f : p3;
    }
}

// ---------------- launch ---------------------------------------------------
extern "C" void kernel_launch(void* const* d_in, const int* in_sizes, int n_in,
                              void* d_out, int out_size) {
    const float* fm   = (const float*)d_in[0];
    const float* wbg  = (const float*)d_in[1];
    const float* mubg = (const float*)d_in[2];
    const float* Lbg  = (const float*)d_in[3];
    const float* wfg  = (const float*)d_in[4];
    const float* mufg = (const float*)d_in[5];
    const float* Lfg  = (const float*)d_in[6];
    float* out = (float*)d_out;

    prep_kernel<<<KCOMP, 128>>>(wbg, mubg, Lbg, wfg, mufg, Lfg);
    pack_kernel<<<9, 256>>>();
    density_kernel<<<NTILES, TPB>>>(fm, out);
}

// round 8
// speedup vs baseline: 1.1600x; 1.0508x over previous
#include <cuda_runtime.h>
#include <cuda_fp16.h>
#include <cstdint>

#define NVOX   (2*96*96*64)   // 1179648
#define TPB    128
#define NTILES (NVOX / TPB)   // 9216
#define KCOMP  16

// B fragments: [kstep 2][ntile 64][lane 32] uint2 (f16 Linv/20, mma col-major frag)
static __device__ uint2  g_Bfrag[2 * 64 * 32];
// acc-init fragments: [ntile 64][colpair 4] float2 = -b/20 for the 2 cols
static __device__ float2 g_bfrag[64 * 4];
static __device__ float  g_a2[KCOMP];

// ---------------- PTX helpers ----------------------------------------------
__device__ __forceinline__ uint32_t smem_u32(const void* p) {
    uint32_t a;
    asm("{ .reg .u64 t; cvta.to.shared.u64 t, %1; cvt.u32.u64 %0, t; }"
        : "=r"(a) : "l"(p));
    return a;
}
#define STS128(r0, r1, r2, r3, a) \
    asm volatile("st.shared.v4.b32 [%0], {%1, %2, %3, %4};" \
                 :: "r"(a), "r"(r0), "r"(r1), "r"(r2), "r"(r3) : "memory")

__device__ __forceinline__ void ldm4(uint32_t* r, uint32_t addr) {
    asm volatile("ldmatrix.sync.aligned.m8n8.x4.shared.b16 {%0,%1,%2,%3}, [%4];"
        : "=r"(r[0]), "=r"(r[1]), "=r"(r[2]), "=r"(r[3]) : "r"(addr));
}
__device__ __forceinline__ void mma16816(float* d, const uint32_t* a,
                                         const uint32_t* b, const float* c) {
    asm volatile("mma.sync.aligned.m16n8k16.row.col.f32.f16.f16.f32 "
        "{%0,%1,%2,%3}, {%4,%5,%6,%7}, {%8,%9}, {%10,%11,%12,%13};"
        : "=f"(d[0]), "=f"(d[1]), "=f"(d[2]), "=f"(d[3])
        : "r"(a[0]), "r"(a[1]), "r"(a[2]), "r"(a[3]),
          "r"(b[0]), "r"(b[1]),
          "f"(c[0]), "f"(c[1]), "f"(c[2]), "f"(c[3]));
}

// ---------------- prep: 16 blocks (one per component) x 128 threads --------
// Inverts L, computes b = Linv*mu, a2, and packs B / acc-init fragments.
__global__ void __launch_bounds__(128)
prep_kernel(const float* __restrict__ wbg,  const float* __restrict__ mubg,
            const float* __restrict__ Lbg,  const float* __restrict__ wfg,
            const float* __restrict__ mufg, const float* __restrict__ Lfg) {
    __shared__ float sL[528];   // L lower triangle
    __shared__ float sT[528];   // Linv lower triangle
    __shared__ float sb[32];
    int k = blockIdx.x;
    int tid = threadIdx.x;
    const float* L  = (k < 8) ? (Lbg  + k * 1024) : (Lfg  + (k - 8) * 1024);
    const float* mu = (k < 8) ? (mubg + k * 32)   : (mufg + (k - 8) * 32);

    for (int e = tid; e < 528; e += 128) {
        int i = (int)((sqrtf(8.0f * e + 1.0f) - 1.0f) * 0.5f);
        while ((i + 1) * (i + 2) / 2 <= e) ++i;
        while (i * (i + 1) / 2 > e) --i;
        int j = e - i * (i + 1) / 2;
        sL[e] = L[i * 32 + j];
    }
    __syncthreads();

    if (tid < 32) {
        int j = tid;
        // forward substitution: column j of Linv, fully register-resident
        float vv[32];
#pragma unroll
        for (int r = 0; r < 32; ++r) {
            float s = 0.0f;
#pragma unroll
            for (int m = 0; m < r; ++m) s += sL[r * (r + 1) / 2 + m] * vv[m];
            float d = sL[r * (r + 1) / 2 + r];
            vv[r] = (r < j) ? 0.0f : ((r == j) ? 1.0f / d : -s / d);
        }
#pragma unroll
        for (int r = 0; r < 32; ++r)
            if (r >= j) sT[r * (r + 1) / 2 + j] = vv[r];
        __syncwarp();
        // b_j = (Linv mu)_j
        float bj = 0.0f;
        for (int c = 0; c <= j; ++c) bj += sT[j * (j + 1) / 2 + c] * mu[c];
        sb[j] = bj;
        // a2 via warp reduction (no bb term: b folded into acc init)
        float lg = logf(sL[j * (j + 1) / 2 + j]);
#pragma unroll
        for (int off = 16; off > 0; off >>= 1)
            lg += __shfl_xor_sync(0xFFFFFFFFu, lg, off);
        if (j == 0) {
            float wk = (k < 8) ? wbg[k] : wfg[k - 8];
            const float cst = -0.5f * 32.0f * 1.8378770664093453f;
            g_a2[k] = wk * expf((cst - lg) * 0.005f);
        }
    }
    __syncthreads();

    // pack B fragments (Linv/20, zero above diagonal)
    for (int idx = tid; idx < 256; idx += 128) {
        int s = idx >> 7, nt4 = (idx >> 5) & 3, lane = idx & 31;
        int d = 8 * nt4 + (lane >> 2);          // output dim for this n
        int t0 = 16 * s + (lane & 3) * 2;       // k index base
        const float* row = sT + d * (d + 1) / 2;
        float v0 = (t0     <= d) ? row[t0]     * 0.05f : 0.0f;
        float v1 = (t0 + 1 <= d) ? row[t0 + 1] * 0.05f : 0.0f;
        float v2 = (t0 + 8 <= d) ? row[t0 + 8] * 0.05f : 0.0f;
        float v3 = (t0 + 9 <= d) ? row[t0 + 9] * 0.05f : 0.0f;
        __half2 lo = __floats2half2_rn(v0, v1);
        __half2 hi = __floats2half2_rn(v2, v3);
        uint2 u;
        u.x = *(uint32_t*)&lo;
        u.y = *(uint32_t*)&hi;
        g_Bfrag[(s * 64 + k * 4 + nt4) * 32 + lane] = u;
    }
    // pack acc-init fragments: -b/20 at the 2 cols of each (ntile, colpair)
    if (tid < 16) {
        int nt4 = tid >> 2, q = tid & 3;
        int d0 = 8 * nt4 + 2 * q;
        g_bfrag[(k * 4 + nt4) * 4 + q] =
            make_float2(-sb[d0] * 0.05f, -sb[d0 + 1] * 0.05f);
    }
}

// ---------------- density: K=32 whitening GEMM + square-reduce -------------
__global__ void __launch_bounds__(TPB, 8)
density_kernel(const float* __restrict__ fm, float* __restrict__ out) {
    __shared__ __align__(1024) char sZ[TPB * 128];   // 16 KB, 128B/row (SW128)

    int tid = threadIdx.x;
    int lane = tid & 31;
    int wid = tid >> 5;
    size_t v0 = (size_t)blockIdx.x * TPB;

    // load x (32 f32), convert to f16, store row to smem (4 STS.128)
    {
        const float4* xf = (const float4*)(fm + (v0 + tid) * 32);
        uint32_t h[16];
#pragma unroll
        for (int q = 0; q < 8; ++q) {
            float4 t4 = xf[q];
            __half2 lo = __floats2half2_rn(t4.x, t4.y);
            __half2 hi = __floats2half2_rn(t4.z, t4.w);
            h[2 * q]     = *(uint32_t*)&lo;
            h[2 * q + 1] = *(uint32_t*)&hi;
        }
        uint32_t x7 = (uint32_t)(tid & 7);
        uint32_t sts_row = smem_u32(sZ) + (uint32_t)tid * 128;
        STS128(h[0],  h[1],  h[2],  h[3],  sts_row + ((0u ^ x7) << 4));
        STS128(h[4],  h[5],  h[6],  h[7],  sts_row + ((1u ^ x7) << 4));
        STS128(h[8],  h[9],  h[10], h[11], sts_row + ((2u ^ x7) << 4));
        STS128(h[12], h[13], h[14], h[15], sts_row + ((3u ^ x7) << 4));
    }
    __syncthreads();

    // A fragments: 2 m-tiles (rows, rows+16) x 2 ksteps, loaded once
    uint32_t Zbase = smem_u32(sZ);
    uint32_t lrow0 = (uint32_t)(wid * 32 + (lane & 7) + ((lane >> 3) & 1) * 8);
    uint32_t colsel = (uint32_t)(lane >> 4);
    uint32_t lx = lrow0 & 7;
    uint32_t ad0 = Zbase + lrow0 * 128;
    uint32_t ad1 = Zbase + (lrow0 + 16) * 128;
    uint32_t a00[4], a01[4], a10[4], a11[4];
    ldm4(a00, ad0 + (((0u + colsel) ^ lx) << 4));
    ldm4(a01, ad0 + (((2u + colsel) ^ lx) << 4));
    ldm4(a10, ad1 + (((0u + colsel) ^ lx) << 4));
    ldm4(a11, ad1 + (((2u + colsel) ^ lx) << 4));

    const uint2*  __restrict__ gB = g_Bfrag;
    const float2* __restrict__ gb = g_bfrag;
    int q3 = lane & 3;

    float dens0 = 0.f, dens1 = 0.f, dens2 = 0.f, dens3 = 0.f;

#pragma unroll 2
    for (int c = 0; c < KCOMP; ++c) {
        float e0 = 0.f, e1 = 0.f, e2 = 0.f, e3 = 0.f;
#pragma unroll
        for (int n4 = 0; n4 < 4; ++n4) {
            int nt = c * 4 + n4;
            uint2 b0 = __ldg(&gB[nt * 32 + lane]);
            uint2 b1 = __ldg(&gB[(64 + nt) * 32 + lane]);
            float2 bi = __ldg(&gb[nt * 4 + q3]);
            float acc0[4] = {bi.x, bi.y, bi.x, bi.y};
            float acc1[4] = {bi.x, bi.y, bi.x, bi.y};
            mma16816(acc0, a00, (uint32_t*)&b0, acc0);
            mma16816(acc0, a01, (uint32_t*)&b1, acc0);
            mma16816(acc1, a10, (uint32_t*)&b0, acc1);
            mma16816(acc1, a11, (uint32_t*)&b1, acc1);
            e0 -= acc0[0] * acc0[0] + acc0[1] * acc0[1];
            e1 -= acc0[2] * acc0[2] + acc0[3] * acc0[3];
            e2 -= acc1[0] * acc1[0] + acc1[1] * acc1[1];
            e3 -= acc1[2] * acc1[2] + acc1[3] * acc1[3];
        }
        // reduce exponent partials over the 4 col-pair lanes
        e0 += __shfl_xor_sync(0xFFFFFFFFu, e0, 1);
        e0 += __shfl_xor_sync(0xFFFFFFFFu, e0, 2);
        e1 += __shfl_xor_sync(0xFFFFFFFFu, e1, 1);
        e1 += __shfl_xor_sync(0xFFFFFFFFu, e1, 2);
        e2 += __shfl_xor_sync(0xFFFFFFFFu, e2, 1);
        e2 += __shfl_xor_sync(0xFFFFFFFFu, e2, 2);
        e3 += __shfl_xor_sync(0xFFFFFFFFu, e3, 1);
        e3 += __shfl_xor_sync(0xFFFFFFFFu, e3, 2);
        float ac = __ldg(&g_a2[c]);
        dens0 += ac * __expf(e0);
        dens1 += ac * __expf(e1);
        dens2 += ac * __expf(e2);
        dens3 += ac * __expf(e3);
    }

    if (q3 == 0) {
        size_t base = v0 + (size_t)wid * 32;
        size_t r0 = base + (lane >> 2);
        size_t r1 = r0 + 8, r2 = r0 + 16, r3 = r0 + 24;
        out[r0] = ((r0 & 63) == 63) ? 0.0f : dens0;
        out[r1] = ((r1 & 63) == 63) ? 0.0f : dens1;
        out[r2] = ((r2 & 63) == 63) ? 0.0f : dens2;
        out[r3] = ((r3 & 63) == 63) ? 0.0f : dens3;
    }
}

// ---------------- launch ---------------------------------------------------
extern "C" void kernel_launch(void* const* d_in, const int* in_sizes, int n_in,
                              void* d_out, int out_size) {
    const float* fm   = (const float*)d_in[0];
    const float* wbg  = (const float*)d_in[1];
    const float* mubg = (const float*)d_in[2];
    const float* Lbg  = (const float*)d_in[3];
    const float* wfg  = (const float*)d_in[4];
    const float* mufg = (const float*)d_in[5];
    const float* Lfg  = (const float*)d_in[6];
    float* out = (float*)d_out;

    prep_kernel<<<KCOMP, 128>>>(wbg, mubg, Lbg, wfg, mufg, Lfg);
    density_kernel<<<NTILES, TPB>>>(fm, out);
}

// round 9
// speedup vs baseline: 1.5194x; 1.3098x over previous
#include <cuda_runtime.h>
#include <cuda_fp16.h>
#include <cstdint>

#define NVOX   (2*96*96*64)   // 1179648
#define TPB    128
#define NTILES (NVOX / TPB)   // 9216
#define KCOMP  16

// B fragments: [kstep 2][ntile 64][lane 32] uint2 (f16 Linv/20).
// Mapping: ntile nt, col p (=lane>>2): comp c = 4*(nt&3) + (p>>1),
//          dim d = 2*(nt>>2) + (p&1), k = 16*s + (lane&3)*2 + {0,1,8,9}.
static __device__ uint2  g_Bfrag[2 * 64 * 32];
// acc-init: [ntile 64][colpair 4] float2 = -b_c[d0..d0+1]/20
static __device__ float2 g_bfrag[64 * 4];
static __device__ float  g_a2[KCOMP];

// ---------------- helpers ---------------------------------------------------
__device__ __forceinline__ uint32_t smem_u32(const void* p) {
    uint32_t a;
    asm("{ .reg .u64 t; cvta.to.shared.u64 t, %1; cvt.u32.u64 %0, t; }"
        : "=r"(a) : "l"(p));
    return a;
}
#define STS128(r0, r1, r2, r3, a) \
    asm volatile("st.shared.v4.b32 [%0], {%1, %2, %3, %4};" \
                 :: "r"(a), "r"(r0), "r"(r1), "r"(r2), "r"(r3) : "memory")

__device__ __forceinline__ void ldm4(uint32_t* r, uint32_t addr) {
    asm volatile("ldmatrix.sync.aligned.m8n8.x4.shared.b16 {%0,%1,%2,%3}, [%4];"
        : "=r"(r[0]), "=r"(r[1]), "=r"(r[2]), "=r"(r[3]) : "r"(addr));
}
__device__ __forceinline__ void mma16816(float* d, const uint32_t* a,
                                         const uint32_t* b, const float* c) {
    asm volatile("mma.sync.aligned.m16n8k16.row.col.f32.f16.f16.f32 "
        "{%0,%1,%2,%3}, {%4,%5,%6,%7}, {%8,%9}, {%10,%11,%12,%13};"
        : "=f"(d[0]), "=f"(d[1]), "=f"(d[2]), "=f"(d[3])
        : "r"(a[0]), "r"(a[1]), "r"(a[2]), "r"(a[3]),
          "r"(b[0]), "r"(b[1]),
          "f"(c[0]), "f"(c[1]), "f"(c[2]), "f"(c[3]));
}
__device__ __forceinline__ unsigned long long pack2(float a, float b) {
    unsigned long long r;
    asm("mov.b64 %0, {%1, %2};" : "=l"(r) : "f"(a), "f"(b));
    return r;
}
__device__ __forceinline__ unsigned long long fma2(unsigned long long a,
                                                   unsigned long long b,
                                                   unsigned long long c) {
    unsigned long long d;
    asm("fma.rn.f32x2 %0, %1, %2, %3;" : "=l"(d) : "l"(a), "l"(b), "l"(c));
    return d;
}
__device__ __forceinline__ void unpack2(unsigned long long v, float& a, float& b) {
    asm("mov.b64 {%0, %1}, %2;" : "=f"(a), "=f"(b) : "l"(v));
}

// ---------------- prep: 16 blocks (one per component) x 128 threads ---------
__global__ void __launch_bounds__(128)
prep_kernel(const float* __restrict__ wbg,  const float* __restrict__ mubg,
            const float* __restrict__ Lbg,  const float* __restrict__ wfg,
            const float* __restrict__ mufg, const float* __restrict__ Lfg) {
    __shared__ float sL[528];
    __shared__ float sT[528];
    __shared__ float sb[32];
    int kc = blockIdx.x;
    int tid = threadIdx.x;
    const float* L  = (kc < 8) ? (Lbg  + kc * 1024) : (Lfg  + (kc - 8) * 1024);
    const float* mu = (kc < 8) ? (mubg + kc * 32)   : (mufg + (kc - 8) * 32);

    for (int e = tid; e < 528; e += 128) {
        int i = (int)((sqrtf(8.0f * e + 1.0f) - 1.0f) * 0.5f);
        while ((i + 1) * (i + 2) / 2 <= e) ++i;
        while (i * (i + 1) / 2 > e) --i;
        int j = e - i * (i + 1) / 2;
        sL[e] = L[i * 32 + j];
    }
    __syncthreads();

    if (tid < 32) {
        int j = tid;
        float vv[32];
#pragma unroll
        for (int r = 0; r < 32; ++r) {
            float s = 0.0f;
#pragma unroll
            for (int m = 0; m < r; ++m) s += sL[r * (r + 1) / 2 + m] * vv[m];
            float d = sL[r * (r + 1) / 2 + r];
            vv[r] = (r < j) ? 0.0f : ((r == j) ? 1.0f / d : -s / d);
        }
#pragma unroll
        for (int r = 0; r < 32; ++r)
            if (r >= j) sT[r * (r + 1) / 2 + j] = vv[r];
        __syncwarp();
        float bj = 0.0f;
        for (int c = 0; c <= j; ++c) bj += sT[j * (j + 1) / 2 + c] * mu[c];
        sb[j] = bj;
        float lg = logf(sL[j * (j + 1) / 2 + j]);
#pragma unroll
        for (int off = 16; off > 0; off >>= 1)
            lg += __shfl_xor_sync(0xFFFFFFFFu, lg, off);
        if (j == 0) {
            float wk = (kc < 8) ? wbg[kc] : wfg[kc - 8];
            const float cst = -0.5f * 32.0f * 1.8378770664093453f;
            g_a2[kc] = wk * expf((cst - lg) * 0.005f);
        }
    }
    __syncthreads();

    // pack B fragments for this component: 2 ksteps x 16 j x 8 lanes = 256
    int qc = kc & 3, ac = kc >> 2;
    for (int idx = tid; idx < 256; idx += 128) {
        int s  = idx >> 7;          // kstep
        int j  = (idx >> 3) & 15;   // dim pair index
        int pl = idx & 7;           // which of the 8 owned lanes
        int p  = 2 * qc + (pl >> 2);    // B col (lane>>2)
        int kq = pl & 3;                // lane&3
        int lane = p * 4 + kq;
        int nt = 4 * j + ac;
        int d  = 2 * j + (p & 1);
        int k0 = 16 * s + kq * 2;
        const float* row = sT + d * (d + 1) / 2;
        float v0 = (k0     <= d) ? row[k0]     * 0.05f : 0.0f;
        float v1 = (k0 + 1 <= d) ? row[k0 + 1] * 0.05f : 0.0f;
        float v2 = (k0 + 8 <= d) ? row[k0 + 8] * 0.05f : 0.0f;
        float v3 = (k0 + 9 <= d) ? row[k0 + 9] * 0.05f : 0.0f;
        __half2 lo = __floats2half2_rn(v0, v1);
        __half2 hi = __floats2half2_rn(v2, v3);
        uint2 u;
        u.x = *(uint32_t*)&lo;
        u.y = *(uint32_t*)&hi;
        g_Bfrag[(s * 64 + nt) * 32 + lane] = u;
    }
    // acc-init fragments: 16 entries (one per j)
    if (tid < 16) {
        int j = tid;
        int nt = 4 * j + ac;
        int d0 = 2 * j;
        g_bfrag[nt * 4 + qc] = make_float2(-sb[d0] * 0.05f, -sb[d0 + 1] * 0.05f);
    }
}

// ---------------- density: K=32 whitening GEMM, lane-local reduction --------
__global__ void __launch_bounds__(TPB, 8)
density_kernel(const float* __restrict__ fm, float* __restrict__ out) {
    __shared__ __align__(1024) char sZ[TPB * 128];

    int tid = threadIdx.x;
    int lane = tid & 31;
    int wid = tid >> 5;
    size_t v0 = (size_t)blockIdx.x * TPB;

    {   // load x, convert f16, store swizzled row
        const float4* xf = (const float4*)(fm + (v0 + tid) * 32);
        uint32_t h[16];
#pragma unroll
        for (int q = 0; q < 8; ++q) {
            float4 t4 = xf[q];
            __half2 lo = __floats2half2_rn(t4.x, t4.y);
            __half2 hi = __floats2half2_rn(t4.z, t4.w);
            h[2 * q]     = *(uint32_t*)&lo;
            h[2 * q + 1] = *(uint32_t*)&hi;
        }
        uint32_t x7 = (uint32_t)(tid & 7);
        uint32_t sts_row = smem_u32(sZ) + (uint32_t)tid * 128;
        STS128(h[0],  h[1],  h[2],  h[3],  sts_row + ((0u ^ x7) << 4));
        STS128(h[4],  h[5],  h[6],  h[7],  sts_row + ((1u ^ x7) << 4));
        STS128(h[8],  h[9],  h[10], h[11], sts_row + ((2u ^ x7) << 4));
        STS128(h[12], h[13], h[14], h[15], sts_row + ((3u ^ x7) << 4));
    }
    __syncthreads();

    // A fragments: 2 m-tiles x 2 ksteps, loaded once
    uint32_t Zbase = smem_u32(sZ);
    uint32_t lrow0 = (uint32_t)(wid * 32 + (lane & 7) + ((lane >> 3) & 1) * 8);
    uint32_t colsel = (uint32_t)(lane >> 4);
    uint32_t lx = lrow0 & 7;
    uint32_t ad0 = Zbase + lrow0 * 128;
    uint32_t ad1 = Zbase + (lrow0 + 16) * 128;
    uint32_t a00[4], a01[4], a10[4], a11[4];
    ldm4(a00, ad0 + (((0u + colsel) ^ lx) << 4));
    ldm4(a01, ad0 + (((2u + colsel) ^ lx) << 4));
    ldm4(a10, ad1 + (((0u + colsel) ^ lx) << 4));
    ldm4(a11, ad1 + (((2u + colsel) ^ lx) << 4));

    const uint2*  __restrict__ gB = g_Bfrag;
    const float2* __restrict__ gb = g_bfrag;
    int q3 = lane & 3;

    float dens0 = 0.f, dens1 = 0.f, dens2 = 0.f, dens3 = 0.f;

#pragma unroll
    for (int a = 0; a < 4; ++a) {
        // packed square-sum accumulators for 4 output rows (this lane's comp)
        unsigned long long e2_0 = 0ull, e2_1 = 0ull, e2_2 = 0ull, e2_3 = 0ull;
#pragma unroll
        for (int j = 0; j < 16; ++j) {
            int nt = 4 * j + a;
            uint2 b0 = __ldg(&gB[nt * 32 + lane]);
            float2 bi = __ldg(&gb[nt * 4 + q3]);
            float acc0[4] = {bi.x, bi.y, bi.x, bi.y};
            float acc1[4] = {bi.x, bi.y, bi.x, bi.y};
            mma16816(acc0, a00, (uint32_t*)&b0, acc0);
            mma16816(acc1, a10, (uint32_t*)&b0, acc1);
            if (j >= 8) {   // kstep 1 nonzero only for dims >= 16
                uint2 b1 = __ldg(&gB[(64 + nt) * 32 + lane]);
                mma16816(acc0, a01, (uint32_t*)&b1, acc0);
                mma16816(acc1, a11, (uint32_t*)&b1, acc1);
            }
            unsigned long long p0 = pack2(acc0[0], acc0[1]);
            unsigned long long p1 = pack2(acc0[2], acc0[3]);
            unsigned long long p2 = pack2(acc1[0], acc1[1]);
            unsigned long long p3 = pack2(acc1[2], acc1[3]);
            e2_0 = fma2(p0, p0, e2_0);
            e2_1 = fma2(p1, p1, e2_1);
            e2_2 = fma2(p2, p2, e2_2);
            e2_3 = fma2(p3, p3, e2_3);
        }
        float ac = __ldg(&g_a2[4 * a + q3]);
        float lo, hi;
        unpack2(e2_0, lo, hi); dens0 += ac * __expf(-(lo + hi));
        unpack2(e2_1, lo, hi); dens1 += ac * __expf(-(lo + hi));
        unpack2(e2_2, lo, hi); dens2 += ac * __expf(-(lo + hi));
        unpack2(e2_3, lo, hi); dens3 += ac * __expf(-(lo + hi));
    }

    // reduce dens over the 4 colpair lanes
    dens0 += __shfl_xor_sync(0xFFFFFFFFu, dens0, 1);
    dens0 += __shfl_xor_sync(0xFFFFFFFFu, dens0, 2);
    dens1 += __shfl_xor_sync(0xFFFFFFFFu, dens1, 1);
    dens1 += __shfl_xor_sync(0xFFFFFFFFu, dens1, 2);
    dens2 += __shfl_xor_sync(0xFFFFFFFFu, dens2, 1);
    dens2 += __shfl_xor_sync(0xFFFFFFFFu, dens2, 2);
    dens3 += __shfl_xor_sync(0xFFFFFFFFu, dens3, 1);
    dens3 += __shfl_xor_sync(0xFFFFFFFFu, dens3, 2);

    if (q3 == 0) {
        size_t base = v0 + (size_t)wid * 32;
        size_t r0 = base + (lane >> 2);
        size_t r1 = r0 + 8, r2 = r0 + 16, r3 = r0 + 24;
        out[r0] = ((r0 & 63) == 63) ? 0.0f : dens0;
        out[r1] = ((r1 & 63) == 63) ? 0.0f : dens1;
        out[r2] = ((r2 & 63) == 63) ? 0.0f : dens2;
        out[r3] = ((r3 & 63) == 63) ? 0.0f : dens3;
    }
}

// ---------------- launch ----------------------------------------------------
extern "C" void kernel_launch(void* const* d_in, const int* in_sizes, int n_in,
                              void* d_out, int out_size) {
    const float* fm   = (const float*)d_in[0];
    const float* wbg  = (const float*)d_in[1];
    const float* mubg = (const float*)d_in[2];
    const float* Lbg  = (const float*)d_in[3];
    const float* wfg  = (const float*)d_in[4];
    const float* mufg = (const float*)d_in[5];
    const float* Lfg  = (const float*)d_in[6];
    float* out = (float*)d_out;

    prep_kernel<<<KCOMP, 128>>>(wbg, mubg, Lbg, wfg, mufg, Lfg);
    density_kernel<<<NTILES, TPB>>>(fm, out);
}

// round 10
// speedup vs baseline: 1.8756x; 1.2345x over previous
#include <cuda_runtime.h>
#include <cuda_fp16.h>
#include <cstdint>

#define NVOX   (2*96*96*64)   // 1179648
#define TPB    128
#define VPC    256            // voxels per CTA
#define NCTA   (NVOX / VPC)   // 4608
#define KCOMP  16

// B fragments: [kstep 2][ntile 64][lane 32] uint2 (f16 Linv/20).
// ntile nt, col p (=lane>>2): comp c = 4*(nt&3) + (p>>1), dim d = 2*(nt>>2) + (p&1)
static __device__ uint2  g_Bfrag[2 * 64 * 32];
static __device__ float2 g_bfrag[64 * 4];   // [ntile][colpair] = -b/20
static __device__ float  g_a2[KCOMP];

// ---------------- helpers ---------------------------------------------------
__device__ __forceinline__ uint32_t smem_u32(const void* p) {
    uint32_t a;
    asm("{ .reg .u64 t; cvta.to.shared.u64 t, %1; cvt.u32.u64 %0, t; }"
        : "=r"(a) : "l"(p));
    return a;
}
__device__ __forceinline__ void ldm4(uint32_t* r, uint32_t addr) {
    asm volatile("ldmatrix.sync.aligned.m8n8.x4.shared.b16 {%0,%1,%2,%3}, [%4];"
        : "=r"(r[0]), "=r"(r[1]), "=r"(r[2]), "=r"(r[3]) : "r"(addr));
}
__device__ __forceinline__ void mma16816(float* d, const uint32_t* a,
                                         const uint32_t* b, const float* c) {
    asm volatile("mma.sync.aligned.m16n8k16.row.col.f32.f16.f16.f32 "
        "{%0,%1,%2,%3}, {%4,%5,%6,%7}, {%8,%9}, {%10,%11,%12,%13};"
        : "=f"(d[0]), "=f"(d[1]), "=f"(d[2]), "=f"(d[3])
        : "r"(a[0]), "r"(a[1]), "r"(a[2]), "r"(a[3]),
          "r"(b[0]), "r"(b[1]),
          "f"(c[0]), "f"(c[1]), "f"(c[2]), "f"(c[3]));
}
__device__ __forceinline__ unsigned long long pack2(float a, float b) {
    unsigned long long r;
    asm("mov.b64 %0, {%1, %2};" : "=l"(r) : "f"(a), "f"(b));
    return r;
}
__device__ __forceinline__ unsigned long long fma2(unsigned long long a,
                                                   unsigned long long b,
                                                   unsigned long long c) {
    unsigned long long d;
    asm("fma.rn.f32x2 %0, %1, %2, %3;" : "=l"(d) : "l"(a), "l"(b), "l"(c));
    return d;
}
__device__ __forceinline__ void unpack2(unsigned long long v, float& a, float& b) {
    asm("mov.b64 {%0, %1}, %2;" : "=f"(a), "=f"(b) : "l"(v));
}

// packed smem addressing: voxel v, 16B-chunk c (0..3):
// line (v>>1) 128B, half (v&1) 64B, chunk swizzled by (v>>1)&3
__device__ __forceinline__ uint32_t zaddr(uint32_t Zb, uint32_t v, uint32_t c) {
    return Zb + (v >> 1) * 128u + (v & 1u) * 64u + (((c ^ (v >> 1)) & 3u) << 4);
}

// ---------------- prep: 16 blocks (one per component) x 128 threads ---------
__global__ void __launch_bounds__(128)
prep_kernel(const float* __restrict__ wbg,  const float* __restrict__ mubg,
            const float* __restrict__ Lbg,  const float* __restrict__ wfg,
            const float* __restrict__ mufg, const float* __restrict__ Lfg) {
    __shared__ float sL[528];
    __shared__ float sT[528];
    __shared__ float sb[32];
    int kc = blockIdx.x;
    int tid = threadIdx.x;
    const float* L  = (kc < 8) ? (Lbg  + kc * 1024) : (Lfg  + (kc - 8) * 1024);
    const float* mu = (kc < 8) ? (mubg + kc * 32)   : (mufg + (kc - 8) * 32);

    for (int e = tid; e < 528; e += 128) {
        int i = (int)((sqrtf(8.0f * e + 1.0f) - 1.0f) * 0.5f);
        while ((i + 1) * (i + 2) / 2 <= e) ++i;
        while (i * (i + 1) / 2 > e) --i;
        int j = e - i * (i + 1) / 2;
        sL[e] = L[i * 32 + j];
    }
    __syncthreads();

    if (tid < 32) {
        int j = tid;
        float vv[32];
#pragma unroll
        for (int r = 0; r < 32; ++r) {
            float s = 0.0f;
#pragma unroll
            for (int m = 0; m < r; ++m) s += sL[r * (r + 1) / 2 + m] * vv[m];
            float d = sL[r * (r + 1) / 2 + r];
            vv[r] = (r < j) ? 0.0f : ((r == j) ? 1.0f / d : -s / d);
        }
#pragma unroll
        for (int r = 0; r < 32; ++r)
            if (r >= j) sT[r * (r + 1) / 2 + j] = vv[r];
        __syncwarp();
        float bj = 0.0f;
        for (int c = 0; c <= j; ++c) bj += sT[j * (j + 1) / 2 + c] * mu[c];
        sb[j] = bj;
        float lg = logf(sL[j * (j + 1) / 2 + j]);
#pragma unroll
        for (int off = 16; off > 0; off >>= 1)
            lg += __shfl_xor_sync(0xFFFFFFFFu, lg, off);
        if (j == 0) {
            float wk = (kc < 8) ? wbg[kc] : wfg[kc - 8];
            const float cst = -0.5f * 32.0f * 1.8378770664093453f;
            g_a2[kc] = wk * expf((cst - lg) * 0.005f);
        }
    }
    __syncthreads();

    int qc = kc & 3, ac = kc >> 2;
    for (int idx = tid; idx < 256; idx += 128) {
        int s  = idx >> 7;
        int j  = (idx >> 3) & 15;
        int pl = idx & 7;
        int p  = 2 * qc + (pl >> 2);
        int kq = pl & 3;
        int lane = p * 4 + kq;
        int nt = 4 * j + ac;
        int d  = 2 * j + (p & 1);
        int k0 = 16 * s + kq * 2;
        const float* row = sT + d * (d + 1) / 2;
        float v0 = (k0     <= d) ? row[k0]     * 0.05f : 0.0f;
        float v1 = (k0 + 1 <= d) ? row[k0 + 1] * 0.05f : 0.0f;
        float v2 = (k0 + 8 <= d) ? row[k0 + 8] * 0.05f : 0.0f;
        float v3 = (k0 + 9 <= d) ? row[k0 + 9] * 0.05f : 0.0f;
        __half2 lo = __floats2half2_rn(v0, v1);
        __half2 hi = __floats2half2_rn(v2, v3);
        uint2 u;
        u.x = *(uint32_t*)&lo;
        u.y = *(uint32_t*)&hi;
        g_Bfrag[(s * 64 + nt) * 32 + lane] = u;
    }
    if (tid < 16) {
        int j = tid;
        int nt = 4 * j + ac;
        int d0 = 2 * j;
        g_bfrag[nt * 4 + qc] = make_float2(-sb[d0] * 0.05f, -sb[d0 + 1] * 0.05f);
    }
}

// ---------------- density: M=64/warp whitening GEMM -------------------------
__global__ void __launch_bounds__(TPB, 5)
density_kernel(const float* __restrict__ fm, float* __restrict__ out) {
    __shared__ __align__(128) char sZ[16384];   // 256 voxels x 64B packed

    int tid = threadIdx.x;
    int lane = tid & 31;
    int wid = tid >> 5;
    size_t v0 = (size_t)blockIdx.x * VPC;
    uint32_t Zb = smem_u32(sZ);

    // coalesced load + f16 convert + packed scatter (conflict-free STS.64)
    {
        const float4* xf = (const float4*)(fm + v0 * 32);
#pragma unroll
        for (int i = 0; i < 16; ++i) {
            int g = i * TPB + tid;          // float4 index in tile (8 per voxel)
            float4 t4 = xf[g];
            __half2 lo = __floats2half2_rn(t4.x, t4.y);
            __half2 hi = __floats2half2_rn(t4.z, t4.w);
            uint32_t ul = *(uint32_t*)&lo, uh = *(uint32_t*)&hi;
            uint32_t v = (uint32_t)(g >> 3);
            uint32_t pos = (uint32_t)(g & 7);       // 8B piece within row
            uint32_t addr = zaddr(Zb, v, pos >> 1) + (pos & 1u) * 8u;
            asm volatile("st.shared.v2.b32 [%0], {%1, %2};"
                         :: "r"(addr), "r"(ul), "r"(uh) : "memory");
        }
    }
    __syncthreads();

    // A fragments: 4 m-tiles x 2 ksteps
    uint32_t colsel = (uint32_t)(lane >> 4);
    uint32_t vrow = (uint32_t)(wid * 64 + (lane & 7) + ((lane >> 3) & 1) * 8);
    uint32_t A[4][2][4];
#pragma unroll
    for (int mt = 0; mt < 4; ++mt) {
        uint32_t v = vrow + mt * 16;
#pragma unroll
        for (int s = 0; s < 2; ++s)
            ldm4(A[mt][s], zaddr(Zb, v, (uint32_t)(s * 2) + colsel));
    }

    const uint2*  __restrict__ gB = g_Bfrag;
    const float2* __restrict__ gb = g_bfrag;
    int q3 = lane & 3;

    float dens[8];
#pragma unroll
    for (int i = 0; i < 8; ++i) dens[i] = 0.0f;

#pragma unroll
    for (int a = 0; a < 4; ++a) {
        unsigned long long e2[8];
#pragma unroll
        for (int i = 0; i < 8; ++i) e2[i] = 0ull;
#pragma unroll
        for (int j = 0; j < 16; ++j) {
            int nt = 4 * j + a;
            uint2 b0 = __ldg(&gB[nt * 32 + lane]);
            float2 bi = __ldg(&gb[nt * 4 + q3]);
            uint2 b1;
            if (j >= 8) b1 = __ldg(&gB[(64 + nt) * 32 + lane]);
#pragma unroll
            for (int mt = 0; mt < 4; ++mt) {
                float acc[4] = {bi.x, bi.y, bi.x, bi.y};
                mma16816(acc, A[mt][0], (uint32_t*)&b0, acc);
                if (j >= 8) mma16816(acc, A[mt][1], (uint32_t*)&b1, acc);
                unsigned long long p0 = pack2(acc[0], acc[1]);
                unsigned long long p1 = pack2(acc[2], acc[3]);
                e2[mt * 2]     = fma2(p0, p0, e2[mt * 2]);
                e2[mt * 2 + 1] = fma2(p1, p1, e2[mt * 2 + 1]);
            }
        }
        float ac = __ldg(&g_a2[4 * a + q3]);
#pragma unroll
        for (int i = 0; i < 8; ++i) {
            float lo, hi;
            unpack2(e2[i], lo, hi);
            dens[i] += ac * __expf(-(lo + hi));
        }
    }

    // reduce over the 4 colpair lanes, store
#pragma unroll
    for (int i = 0; i < 8; ++i) {
        float d = dens[i];
        d += __shfl_xor_sync(0xFFFFFFFFu, d, 1);
        d += __shfl_xor_sync(0xFFFFFFFFu, d, 2);
        if (q3 == 0) {
            int mt = i >> 1, h = i & 1;
            size_t r = v0 + (size_t)(wid * 64 + mt * 16 + h * 8 + (lane >> 2));
            out[r] = ((r & 63) == 63) ? 0.0f : d;
        }
    }
}

// ---------------- launch ----------------------------------------------------
extern "C" void kernel_launch(void* const* d_in, const int* in_sizes, int n_in,
                              void* d_out, int out_size) {
    const float* fm   = (const float*)d_in[0];
    const float* wbg  = (const float*)d_in[1];
    const float* mubg = (const float*)d_in[2];
    const float* Lbg  = (const float*)d_in[3];
    const float* wfg  = (const float*)d_in[4];
    const float* mufg = (const float*)d_in[5];
    const float* Lfg  = (const float*)d_in[6];
    float* out = (float*)d_out;

    prep_kernel<<<KCOMP, 128>>>(wbg, mubg, Lbg, wfg, mufg, Lfg);
    density_kernel<<<NCTA, TPB>>>(fm, out);
}